// round 13
// baseline (speedup 1.0000x reference)
#include <cuda_runtime.h>

#define BB 4096
#define PP 128
#define GG 128

#define SCX (8000.0f / 79.0f)
#define SCY (8000.0f / 79.0f)
#define SCZ (2000.0f / 19.0f)
#define BX (-4000.0f)
#define BY (-4000.0f)
#define BZ (0.0f)

#define DIST_THRESH_SQ (500.0f * 500.0f)
#define BBOX_THRESH 0.1f
#define EOFF 2.0e8f               // keeps e strictly positive for all finite inputs

typedef unsigned long long ull;

// ---- packed f32x2 helpers (sm_103a) ----
__device__ __forceinline__ ull pack2(float lo, float hi) {
    ull r;
    asm("mov.b64 %0, {%1, %2};" : "=l"(r) : "f"(lo), "f"(hi));
    return r;
}
__device__ __forceinline__ void unpack2(ull v, float& lo, float& hi) {
    asm("mov.b64 {%0, %1}, %2;" : "=f"(lo), "=f"(hi) : "l"(v));
}
__device__ __forceinline__ ull fma2(ull a, ull b, ull c) {
    ull r;
    asm("fma.rn.f32x2 %0, %1, %2, %3;" : "=l"(r) : "l"(a), "l"(b), "l"(c));
    return r;
}
// key = (bits(e) & ~127) | g  in one LOP3 (g < 128 fits low 7 bits)
__device__ __forceinline__ int keyfuse(float s, int g) {
    int r;
    asm("lop3.b32 %0, %1, %2, %3, 0xea;"   // (a & b) | c
        : "=r"(r) : "r"(__float_as_int(s)), "n"(~127), "r"(g));
    return r;
}

__global__ __launch_bounds__(PP, 12)
void proposal_layer_kernel(const int*   __restrict__ topk_index,      // [B,P,3]
                           const float* __restrict__ topk_confs,      // [B,P]
                           const float* __restrict__ match_bbox_preds,// [B,P,2]
                           const float* __restrict__ roots_3d,        // [B,G,3]
                           const float* __restrict__ gt_bbox,         // [B,G,2]
                           const int*   __restrict__ num_person,      // [B]
                           float*       __restrict__ out)             // [B,P,7]
{
    const int b = blockIdx.x;
    const int t = threadIdx.x;  // 0..127, one proposal per thread

    __shared__ __align__(16) float s_nx[GG];   // -rx
    __shared__ __align__(16) float s_ny[GG];   // -ry
    __shared__ __align__(16) float s_nz[GG];   // -rz
    __shared__ __align__(16) float s_h [GG];   // |r|^2/2 + EOFF, +INF for g >= n
    __shared__ float2 s_bbox[GG];
    __shared__ __align__(16) float4 s_out4[224];  // [P,7] output staging

    const int n = num_person[b];  // uniform, broadcast

    // ---- stage gt data; pad h with +INF past n ----
    {
        const float* r = roots_3d + ((size_t)b * GG + t) * 3;
        float rx = r[0], ry = r[1], rz = r[2];
        s_nx[t] = -rx;
        s_ny[t] = -ry;
        s_nz[t] = -rz;
        float hv = __fmaf_rn(0.5f, __fmaf_rn(rz, rz, __fmaf_rn(ry, ry, rx * rx)), EOFF);
        s_h[t]  = (t < n) ? hv : __int_as_float(0x7F800000);
        const float* gb = gt_bbox + ((size_t)b * GG + t) * 2;
        s_bbox[t] = make_float2(gb[0], gb[1]);
    }
    __syncthreads();

    // ---- per-proposal inputs (all before scan; latency overlaps) ----
    const int* ti = topk_index + ((size_t)b * PP + t) * 3;
    const float cx = (float)ti[0] * SCX + BX;
    const float cy = (float)ti[1] * SCY + BY;
    const float cz = (float)ti[2] * SCZ + BZ;

    const float conf = topk_confs[(size_t)b * PP + t];
    const float* mp = match_bbox_preds + ((size_t)b * PP + t) * 2;
    const float pb0 = mp[0];
    const float pb1 = mp[1];

    const ull cxx = pack2(cx, cx);
    const ull cyy = pack2(cy, cy);
    const ull czz = pack2(cz, cz);

    const ulonglong2* px = (const ulonglong2*)s_nx;
    const ulonglong2* py = (const ulonglong2*)s_ny;
    const ulonglong2* pz = (const ulonglong2*)s_nz;
    const ulonglong2* ph = (const ulonglong2*)s_h;

    // ---- FIXED-TRIP scan: all 32 chunks, fully unrolled, single key chain ----
    // key = (bits(e)&~127) | g : smaller e wins; ties -> smaller g (first-min).
    // INF-padded g >= n can never win (bits(INF) > any finite e's bits).
    int bk = 0x7FFFFFFF;
    #pragma unroll
    for (int q = 0; q < GG / 4; ++q) {
        ulonglong2 X = px[q];   // LDS.128 broadcast, immediate offsets
        ulonglong2 Y = py[q];
        ulonglong2 Z = pz[q];
        ulonglong2 H = ph[q];

        ull eA = fma2(cxx, X.x, fma2(cyy, Y.x, fma2(czz, Z.x, H.x)));
        ull eB = fma2(cxx, X.y, fma2(cyy, Y.y, fma2(czz, Z.y, H.y)));
        float s0, s1, s2, s3;
        unpack2(eA, s0, s1);
        unpack2(eB, s2, s3);

        const int g0 = q << 2;
        int m01 = min(keyfuse(s0, g0),     keyfuse(s1, g0 + 1));
        int m23 = min(keyfuse(s2, g0 + 2), keyfuse(s3, g0 + 3));
        bk = min(bk, min(m01, m23));
    }
    const int bi = bk & 127;   // argmin g (valid: n >= 1 and pads never win)

    // ---- exact fp32 threshold recheck (independent of key masking) ----
    // d2 <= 500^2  <=>  e+EOFF <= 0.5*(500^2 - cc) + EOFF
    const float cc = __fmaf_rn(cz, cz, __fmaf_rn(cy, cy, cx * cx));
    const float e_best = __fmaf_rn(cx, s_nx[bi],
                        __fmaf_rn(cy, s_ny[bi],
                        __fmaf_rn(cz, s_nz[bi], s_h[bi])));
    const float thresh_e = __fmaf_rn(-0.5f, cc, 0.5f * DIST_THRESH_SQ + EOFF);
    const bool matched = !(e_best > thresh_e);
    const float p2g = matched ? (float)bi : -1.0f;

    float2 mb = s_bbox[bi];
    bool ow = matched && ((pb0 < mb.x - BBOX_THRESH) || (pb1 < mb.y - BBOX_THRESH));
    const float o5 = ow ? mb.x : pb0;
    const float o6 = ow ? mb.y : pb1;

    // ---- stage [P,7] tile (stride 7 -> conflict-free), float4 store ----
    float* so = (float*)s_out4 + t * 7;
    so[0] = cx; so[1] = cy; so[2] = cz;
    so[3] = p2g; so[4] = conf;
    so[5] = o5;  so[6] = o6;
    __syncthreads();

    float4* dst = (float4*)(out + (size_t)b * (PP * 7));
    #pragma unroll
    for (int i = t; i < 224; i += PP)   // 896 floats = 224 float4
        dst[i] = s_out4[i];
}

extern "C" void kernel_launch(void* const* d_in, const int* in_sizes, int n_in,
                              void* d_out, int out_size)
{
    const int*   topk_index       = (const int*)  d_in[0];
    const float* topk_confs       = (const float*)d_in[1];
    const float* match_bbox_preds = (const float*)d_in[2];
    const float* roots_3d         = (const float*)d_in[3];
    const float* gt_bbox          = (const float*)d_in[4];
    const int*   num_person       = (const int*)  d_in[5];
    float* out = (float*)d_out;

    proposal_layer_kernel<<<BB, PP>>>(topk_index, topk_confs, match_bbox_preds,
                                      roots_3d, gt_bbox, num_person, out);
}

// round 14
// speedup vs baseline: 1.3977x; 1.3977x over previous
#include <cuda_runtime.h>

#define BB 4096
#define PP 128
#define GG 128

#define SCX (8000.0f / 79.0f)
#define SCY (8000.0f / 79.0f)
#define SCZ (2000.0f / 19.0f)
#define BX (-4000.0f)
#define BY (-4000.0f)
#define BZ (0.0f)

#define DIST_THRESH_SQ (500.0f * 500.0f)
#define BBOX_THRESH 0.1f
#define EOFF 2.0e8f              // keeps e strictly positive for all finite inputs
#define KEYMASK (~31)            // drop low 5 float bits, embed q (q < 32)

typedef unsigned long long ull;

// ---- packed f32x2 helpers (sm_103a) ----
__device__ __forceinline__ ull pack2(float lo, float hi) {
    ull r;
    asm("mov.b64 %0, {%1, %2};" : "=l"(r) : "f"(lo), "f"(hi));
    return r;
}
__device__ __forceinline__ void unpack2(ull v, float& lo, float& hi) {
    asm("mov.b64 {%0, %1}, %2;" : "=f"(lo), "=f"(hi) : "l"(v));
}
__device__ __forceinline__ ull fma2(ull a, ull b, ull c) {
    ull r;
    asm("fma.rn.f32x2 %0, %1, %2, %3;" : "=l"(r) : "l"(a), "l"(b), "l"(c));
    return r;
}
// (bits(s) & KEYMASK) | q in a single LOP3
__device__ __forceinline__ int keyfuse(float s, int q) {
    int r;
    asm("lop3.b32 %0, %1, %2, %3, 0xea;"   // (a & b) | c
        : "=r"(r) : "r"(__float_as_int(s)), "n"(KEYMASK), "r"(q));
    return r;
}

__device__ __forceinline__ unsigned smem_u32(const void* p) {
    return (unsigned)__cvta_generic_to_shared(p);
}
// 1-D TMA bulk copy global -> shared::cta, completion via mbarrier tx bytes
__device__ __forceinline__ void bulk_g2s(void* sdst, const void* gsrc,
                                         unsigned bytes, unsigned mbar) {
    asm volatile(
        "cp.async.bulk.shared::cluster.global.mbarrier::complete_tx::bytes "
        "[%0], [%1], %2, [%3];"
        :: "r"(smem_u32(sdst)), "l"(gsrc), "r"(bytes), "r"(mbar) : "memory");
}

struct __align__(16) RawBuf {     // exactly 5632 bytes of bulk-copied data
    float roots[GG * 3];   // 1536 B
    float bbox [GG * 2];   // 1024 B
    int   tidx [PP * 3];   // 1536 B
    float conf [PP];       //  512 B
    float match[PP * 2];   // 1024 B
};
#define TX_BYTES 5632u

__global__ __launch_bounds__(PP, 8)
void proposal_layer_kernel(const int*   __restrict__ topk_index,      // [B,P,3]
                           const float* __restrict__ topk_confs,      // [B,P]
                           const float* __restrict__ match_bbox_preds,// [B,P,2]
                           const float* __restrict__ roots_3d,        // [B,G,3]
                           const float* __restrict__ gt_bbox,         // [B,G,2]
                           const int*   __restrict__ num_person,      // [B]
                           float*       __restrict__ out)             // [B,P,7]
{
    const int b = blockIdx.x;
    const int t = threadIdx.x;  // 0..127, one proposal per thread

    __shared__ RawBuf raw;
    __shared__ __align__(8) ull mbar;
    __shared__ __align__(16) float s_nx[GG];
    __shared__ __align__(16) float s_ny[GG];
    __shared__ __align__(16) float s_nz[GG];
    __shared__ __align__(16) float s_h [GG];
    __shared__ float2 s_bbox[GG];
    __shared__ __align__(16) float4 s_out4[224];

    // ---- one-thread TMA bulk staging of ALL inputs (zero per-thread LDGs) ----
    const unsigned mb = smem_u32(&mbar);
    if (t == 0) {
        asm volatile("mbarrier.init.shared.b64 [%0], %1;" :: "r"(mb), "r"(1u) : "memory");
    }
    __syncthreads();
    if (t == 0) {
        asm volatile("mbarrier.arrive.expect_tx.shared.b64 _, [%0], %1;"
                     :: "r"(mb), "r"(TX_BYTES) : "memory");
        bulk_g2s(raw.roots, roots_3d         + (size_t)b * (GG * 3), 1536u, mb);
        bulk_g2s(raw.bbox,  gt_bbox          + (size_t)b * (GG * 2), 1024u, mb);
        bulk_g2s(raw.tidx,  topk_index       + (size_t)b * (PP * 3), 1536u, mb);
        bulk_g2s(raw.conf,  topk_confs       + (size_t)b * PP,        512u, mb);
        bulk_g2s(raw.match, match_bbox_preds + (size_t)b * (PP * 2), 1024u, mb);
    }
    const int n = num_person[b];  // single uniform LDG (overlaps the DMA)

    // wait for all 5632 bytes (acquire orders subsequent smem reads)
    {
        unsigned done;
        asm volatile(
            "{\n\t.reg .pred p;\n\t"
            "mbarrier.try_wait.parity.acquire.cta.shared::cta.b64 p, [%1], 0;\n\t"
            "selp.b32 %0, 1, 0, p;\n\t}"
            : "=r"(done) : "r"(mb) : "memory");
        if (!done) {
            asm volatile(
                "{\n\t.reg .pred P1;\n\t"
                "W%=:\n\t"
                "mbarrier.try_wait.parity.acquire.cta.shared::cta.b64 P1, [%0], 0, 0x989680;\n\t"
                "@P1 bra.uni D%=;\n\t"
                "bra.uni W%=;\n\t"
                "D%=:\n\t}"
                :: "r"(mb) : "memory");
        }
    }

    // ---- convert raw -> SoA (stride-3/2 LDS, conflict-free or 2-way) ----
    {
        float rx = raw.roots[3 * t], ry = raw.roots[3 * t + 1], rz = raw.roots[3 * t + 2];
        s_nx[t] = -rx;
        s_ny[t] = -ry;
        s_nz[t] = -rz;
        float hv = __fmaf_rn(0.5f, __fmaf_rn(rz, rz, __fmaf_rn(ry, ry, rx * rx)), EOFF);
        s_h[t]  = (t < n) ? hv : __int_as_float(0x7F800000);
        s_bbox[t] = make_float2(raw.bbox[2 * t], raw.bbox[2 * t + 1]);
    }
    const float cx = (float)raw.tidx[3 * t]     * SCX + BX;
    const float cy = (float)raw.tidx[3 * t + 1] * SCY + BY;
    const float cz = (float)raw.tidx[3 * t + 2] * SCZ + BZ;
    const float conf = raw.conf[t];
    const float pb0  = raw.match[2 * t];
    const float pb1  = raw.match[2 * t + 1];
    __syncthreads();

    // ---- scan (champion form): 4 int-key chains over INF-padded chunks ----
    const ull cxx = pack2(cx, cx);
    const ull cyy = pack2(cy, cy);
    const ull czz = pack2(cz, cz);

    const ulonglong2* px = (const ulonglong2*)s_nx;
    const ulonglong2* py = (const ulonglong2*)s_ny;
    const ulonglong2* pz = (const ulonglong2*)s_nz;
    const ulonglong2* ph = (const ulonglong2*)s_h;

    int bk0 = 0x7FFFFFFF, bk1 = 0x7FFFFFFF, bk2 = 0x7FFFFFFF, bk3 = 0x7FFFFFFF;
    const int nbc = (n + 3) >> 2;   // ceil(n/4); INF pads never win
    #pragma unroll 2
    for (int q = 0; q < nbc; ++q) {
        ulonglong2 X = px[q];   // LDS.128 broadcast
        ulonglong2 Y = py[q];
        ulonglong2 Z = pz[q];
        ulonglong2 H = ph[q];

        ull eA = fma2(cxx, X.x, fma2(cyy, Y.x, fma2(czz, Z.x, H.x)));
        ull eB = fma2(cxx, X.y, fma2(cyy, Y.y, fma2(czz, Z.y, H.y)));
        float s0, s1, s2, s3;
        unpack2(eA, s0, s1);
        unpack2(eB, s2, s3);

        bk0 = min(bk0, keyfuse(s0, q));
        bk1 = min(bk1, keyfuse(s1, q));
        bk2 = min(bk2, keyfuse(s2, q));
        bk3 = min(bk3, keyfuse(s3, q));
    }

    // merge chains (masked value, strict <; residue order = g order)
    int best_mv = bk0 & KEYMASK;
    int bi = ((bk0 & 31) << 2);
    { int mv = bk1 & KEYMASK; if (mv < best_mv) { best_mv = mv; bi = ((bk1 & 31) << 2) + 1; } }
    { int mv = bk2 & KEYMASK; if (mv < best_mv) { best_mv = mv; bi = ((bk2 & 31) << 2) + 2; } }
    { int mv = bk3 & KEYMASK; if (mv < best_mv) { best_mv = mv; bi = ((bk3 & 31) << 2) + 3; } }

    // ---- exact fp32 threshold recheck for chosen bi ----
    // d2 <= 500^2  <=>  e+EOFF <= 0.5*(500^2 - cc) + EOFF
    const float cc = __fmaf_rn(cz, cz, __fmaf_rn(cy, cy, cx * cx));
    const float e_best = __fmaf_rn(cx, s_nx[bi],
                        __fmaf_rn(cy, s_ny[bi],
                        __fmaf_rn(cz, s_nz[bi], s_h[bi])));
    const float thresh_e = __fmaf_rn(-0.5f, cc, 0.5f * DIST_THRESH_SQ + EOFF);
    const bool matched = !(e_best > thresh_e);
    const float p2g = matched ? (float)bi : -1.0f;

    float2 mb2 = s_bbox[bi];
    bool ow = matched && ((pb0 < mb2.x - BBOX_THRESH) || (pb1 < mb2.y - BBOX_THRESH));
    const float o5 = ow ? mb2.x : pb0;
    const float o6 = ow ? mb2.y : pb1;

    // ---- stage [P,7] tile (stride 7 -> conflict-free), float4 store ----
    float* so = (float*)s_out4 + t * 7;
    so[0] = cx; so[1] = cy; so[2] = cz;
    so[3] = p2g; so[4] = conf;
    so[5] = o5;  so[6] = o6;
    __syncthreads();

    float4* dst = (float4*)(out + (size_t)b * (PP * 7));
    #pragma unroll
    for (int i = t; i < 224; i += PP)   // 896 floats = 224 float4
        dst[i] = s_out4[i];
}

extern "C" void kernel_launch(void* const* d_in, const int* in_sizes, int n_in,
                              void* d_out, int out_size)
{
    const int*   topk_index       = (const int*)  d_in[0];
    const float* topk_confs       = (const float*)d_in[1];
    const float* match_bbox_preds = (const float*)d_in[2];
    const float* roots_3d         = (const float*)d_in[3];
    const float* gt_bbox          = (const float*)d_in[4];
    const int*   num_person       = (const int*)  d_in[5];
    float* out = (float*)d_out;

    proposal_layer_kernel<<<BB, PP>>>(topk_index, topk_confs, match_bbox_preds,
                                      roots_3d, gt_bbox, num_person, out);
}

// round 15
// speedup vs baseline: 1.4004x; 1.0019x over previous
#include <cuda_runtime.h>

#define BB 4096
#define PP 128
#define GG 128

#define SCX (8000.0f / 79.0f)
#define SCY (8000.0f / 79.0f)
#define SCZ (2000.0f / 19.0f)
#define BX (-4000.0f)
#define BY (-4000.0f)
#define BZ (0.0f)

#define DIST_THRESH_SQ (500.0f * 500.0f)
#define BBOX_THRESH 0.1f
#define EOFF 2.0e8f              // keeps e strictly positive for all finite inputs
#define KEYMASK (~31)            // drop low 5 float bits, embed q (q < 32)

typedef unsigned long long ull;

// ---- packed f32x2 helpers (sm_103a) ----
__device__ __forceinline__ ull pack2(float lo, float hi) {
    ull r;
    asm("mov.b64 %0, {%1, %2};" : "=l"(r) : "f"(lo), "f"(hi));
    return r;
}
__device__ __forceinline__ void unpack2(ull v, float& lo, float& hi) {
    asm("mov.b64 {%0, %1}, %2;" : "=f"(lo), "=f"(hi) : "l"(v));
}
__device__ __forceinline__ ull fma2(ull a, ull b, ull c) {
    ull r;
    asm("fma.rn.f32x2 %0, %1, %2, %3;" : "=l"(r) : "l"(a), "l"(b), "l"(c));
    return r;
}
// (bits(s) & KEYMASK) | q in a single LOP3
__device__ __forceinline__ int keyfuse(float s, int q) {
    int r;
    asm("lop3.b32 %0, %1, %2, %3, 0xea;"   // (a & b) | c
        : "=r"(r) : "r"(__float_as_int(s)), "n"(KEYMASK), "r"(q));
    return r;
}

__global__ __launch_bounds__(PP, 12)   // cap regs ~42 -> 12 CTAs/SM, 48 warps
void proposal_layer_kernel(const int*   __restrict__ topk_index,      // [B,P,3]
                           const float* __restrict__ topk_confs,      // [B,P]
                           const float* __restrict__ match_bbox_preds,// [B,P,2]
                           const float* __restrict__ roots_3d,        // [B,G,3]
                           const float* __restrict__ gt_bbox,         // [B,G,2]
                           const int*   __restrict__ num_person,      // [B]
                           float*       __restrict__ out)             // [B,P,7]
{
    const int b = blockIdx.x;
    const int t = threadIdx.x;  // 0..127, one proposal per thread

    __shared__ __align__(16) float s_nx[GG];   // -rx
    __shared__ __align__(16) float s_ny[GG];   // -ry
    __shared__ __align__(16) float s_nz[GG];   // -rz
    __shared__ __align__(16) float s_h [GG];   // |r|^2/2 + EOFF, +INF for g >= n
    __shared__ float2 s_bbox[GG];
    __shared__ __align__(16) float4 s_out4[224];

    const int n = num_person[b];  // uniform, broadcast

    // ---- stage gt data; pad h with +INF past n (no tail loop) ----
    {
        const float* r = roots_3d + ((size_t)b * GG + t) * 3;
        float rx = r[0], ry = r[1], rz = r[2];
        s_nx[t] = -rx;
        s_ny[t] = -ry;
        s_nz[t] = -rz;
        float hv = __fmaf_rn(0.5f, __fmaf_rn(rz, rz, __fmaf_rn(ry, ry, rx * rx)), EOFF);
        s_h[t]  = (t < n) ? hv : __int_as_float(0x7F800000);
        const float* gb = gt_bbox + ((size_t)b * GG + t) * 2;
        s_bbox[t] = make_float2(gb[0], gb[1]);
    }
    __syncthreads();

    // ---- proposal coords only (conf/match deferred: fewer live regs in scan) ----
    const int* ti = topk_index + ((size_t)b * PP + t) * 3;
    const float cx = (float)ti[0] * SCX + BX;
    const float cy = (float)ti[1] * SCY + BY;
    const float cz = (float)ti[2] * SCZ + BZ;

    const ull cxx = pack2(cx, cx);
    const ull cyy = pack2(cy, cy);
    const ull czz = pack2(cz, cz);

    const ulonglong2* px = (const ulonglong2*)s_nx;
    const ulonglong2* py = (const ulonglong2*)s_ny;
    const ulonglong2* pz = (const ulonglong2*)s_nz;
    const ulonglong2* ph = (const ulonglong2*)s_h;

    // ---- scan: 4 int-key chains; key = (bits(e)&~31) | q, IMNMX update ----
    int bk0 = 0x7FFFFFFF, bk1 = 0x7FFFFFFF, bk2 = 0x7FFFFFFF, bk3 = 0x7FFFFFFF;

    const int nbc = (n + 3) >> 2;   // ceil(n/4); INF pads never win
    #pragma unroll 2
    for (int q = 0; q < nbc; ++q) {
        ulonglong2 X = px[q];   // LDS.128 broadcast
        ulonglong2 Y = py[q];
        ulonglong2 Z = pz[q];
        ulonglong2 H = ph[q];

        ull eA = fma2(cxx, X.x, fma2(cyy, Y.x, fma2(czz, Z.x, H.x)));
        ull eB = fma2(cxx, X.y, fma2(cyy, Y.y, fma2(czz, Z.y, H.y)));
        float s0, s1, s2, s3;
        unpack2(eA, s0, s1);
        unpack2(eB, s2, s3);

        bk0 = min(bk0, keyfuse(s0, q));   // LOP3 + IMNMX per element
        bk1 = min(bk1, keyfuse(s1, q));
        bk2 = min(bk2, keyfuse(s2, q));
        bk3 = min(bk3, keyfuse(s3, q));
    }

    // ---- merge chains: masked values, strict < (residue order = g order) ----
    int best_mv = bk0 & KEYMASK;
    int bi = ((bk0 & 31) << 2);
    { int mv = bk1 & KEYMASK; if (mv < best_mv) { best_mv = mv; bi = ((bk1 & 31) << 2) + 1; } }
    { int mv = bk2 & KEYMASK; if (mv < best_mv) { best_mv = mv; bi = ((bk2 & 31) << 2) + 2; } }
    { int mv = bk3 & KEYMASK; if (mv < best_mv) { best_mv = mv; bi = ((bk3 & 31) << 2) + 3; } }

    // ---- deferred per-proposal loads (L2-latency hidden by other warps) ----
    const float conf = topk_confs[(size_t)b * PP + t];
    const float* mp = match_bbox_preds + ((size_t)b * PP + t) * 2;
    const float pb0 = mp[0];
    const float pb1 = mp[1];

    // ---- exact fp32 threshold recheck for chosen bi ----
    // d2 <= 500^2  <=>  e+EOFF <= 0.5*(500^2 - cc) + EOFF
    const float cc = __fmaf_rn(cz, cz, __fmaf_rn(cy, cy, cx * cx));
    const float e_best = __fmaf_rn(cx, s_nx[bi],
                        __fmaf_rn(cy, s_ny[bi],
                        __fmaf_rn(cz, s_nz[bi], s_h[bi])));
    const float thresh_e = __fmaf_rn(-0.5f, cc, 0.5f * DIST_THRESH_SQ + EOFF);
    const bool matched = !(e_best > thresh_e);
    const float p2g = matched ? (float)bi : -1.0f;

    float2 mb = s_bbox[bi];
    bool ow = matched && ((pb0 < mb.x - BBOX_THRESH) || (pb1 < mb.y - BBOX_THRESH));
    const float o5 = ow ? mb.x : pb0;
    const float o6 = ow ? mb.y : pb1;

    // ---- stage [P,7] tile (stride 7 -> conflict-free), float4 store ----
    float* so = (float*)s_out4 + t * 7;
    so[0] = cx; so[1] = cy; so[2] = cz;
    so[3] = p2g; so[4] = conf;
    so[5] = o5;  so[6] = o6;
    __syncthreads();

    float4* dst = (float4*)(out + (size_t)b * (PP * 7));
    #pragma unroll
    for (int i = t; i < 224; i += PP)   // 896 floats = 224 float4
        dst[i] = s_out4[i];
}

extern "C" void kernel_launch(void* const* d_in, const int* in_sizes, int n_in,
                              void* d_out, int out_size)
{
    const int*   topk_index       = (const int*)  d_in[0];
    const float* topk_confs       = (const float*)d_in[1];
    const float* match_bbox_preds = (const float*)d_in[2];
    const float* roots_3d         = (const float*)d_in[3];
    const float* gt_bbox          = (const float*)d_in[4];
    const int*   num_person       = (const int*)  d_in[5];
    float* out = (float*)d_out;

    proposal_layer_kernel<<<BB, PP>>>(topk_index, topk_confs, match_bbox_preds,
                                      roots_3d, gt_bbox, num_person, out);
}